// round 12
// baseline (speedup 1.0000x reference)
#include <cuda_runtime.h>
#include <cstdint>

#define MAXN 50000
#define MAXE 1600000

// ---- scratch (static device globals: allocation-free) ----
// INVARIANT: g_deg/g_cur are zero at every kernel_launch entry (statically
// zero-initialized; final_kernel re-zeros them at the end of each call).
// g_se is padded by 32 entries (always zero => src 0 / edge 0: valid reads)
// so gather lookahead loads need no clamping.
__device__ float g_h [MAXN * 128];
__device__ float g_hA[MAXN * 128];
__device__ float g_hB[MAXN * 128];
__device__ int   g_deg[MAXN];
__device__ int   g_cur[MAXN];
__device__ int   g_rowptr[MAXN + 1];
__device__ int   g_src[MAXE];
__device__ int   g_dst[MAXE];
__device__ int2  g_se[MAXE + 32];   // (src, edge_id) sorted by dst, padded

// ---- packed f32x2 helpers ----
typedef unsigned long long u64;

__device__ __forceinline__ u64 pack2(float lo, float hi) {
    u64 r;
    asm("mov.b64 %0, {%1, %2};" : "=l"(r) : "f"(lo), "f"(hi));
    return r;
}
__device__ __forceinline__ void unpack2(u64 v, float& lo, float& hi) {
    asm("mov.b64 {%0, %1}, %2;" : "=f"(lo), "=f"(hi) : "l"(v));
}
__device__ __forceinline__ u64 ffma2(u64 a, u64 b, u64 c) {
    u64 d;
    asm("fma.rn.f32x2 %0, %1, %2, %3;" : "=l"(d) : "l"(a), "l"(b), "l"(c));
    return d;
}

// ---- cp.async helpers (smem address precomputed as u32) ----
__device__ __forceinline__ void cp_async16s(unsigned sdst, const void* src) {
    asm volatile("cp.async.cg.shared.global [%0], [%1], 16;" :: "r"(sdst), "l"(src));
}
__device__ __forceinline__ void cp_commit() {
    asm volatile("cp.async.commit_group;");
}
template <int N> __device__ __forceinline__ void cp_wait() {
    asm volatile("cp.async.wait_group %0;" :: "n"(N));
}

// ---------------------------------------------------------------------------
// Launch 1: convert edge_index to int32 (+dtype sniff per block) + dst histogram
// ---------------------------------------------------------------------------
__global__ void convert_hist_kernel(const void* __restrict__ ei, int E_, int N_) {
    __shared__ int bad;
    if (threadIdx.x == 0) bad = 0;
    __syncthreads();
    const long long* p64 = (const long long*)ei;
    int cnt = 0;
    for (int i = threadIdx.x; i < 512; i += blockDim.x) {
        long long v = p64[i];
        if (v < 0 || v >= (long long)N_) cnt++;
    }
    if (cnt) atomicAdd(&bad, cnt);
    __syncthreads();
    bool is64 = (bad < 256);

    int e = blockIdx.x * blockDim.x + threadIdx.x;
    if (e >= E_) return;
    int s, d;
    if (is64) {
        s = (int)p64[e]; d = (int)p64[E_ + e];
    } else {
        const int* p = (const int*)ei;
        s = p[e]; d = p[E_ + e];
    }
    g_src[e] = s;
    g_dst[e] = d;
    atomicAdd(&g_deg[d], 1);
}

// ---------------------------------------------------------------------------
// Launch 2: single-block exclusive scan of g_deg -> g_rowptr
// ---------------------------------------------------------------------------
__global__ void __launch_bounds__(1024) scan_kernel(int N_) {
    __shared__ int sh[1024];
    int tid = threadIdx.x;
    int chunk = (N_ + 1023) / 1024;
    int lo = tid * chunk;
    int hi = min(lo + chunk, N_);

    int sum = 0;
    for (int i = lo; i < hi; i++) sum += g_deg[i];
    sh[tid] = sum;
    __syncthreads();
    #pragma unroll
    for (int off = 1; off < 1024; off <<= 1) {
        int t = (tid >= off) ? sh[tid - off] : 0;
        __syncthreads();
        sh[tid] += t;
        __syncthreads();
    }
    int run = (tid > 0) ? sh[tid - 1] : 0;
    for (int i = lo; i < hi; i++) {
        run += g_deg[i];
        g_rowptr[i + 1] = run;
    }
    if (tid == 0) g_rowptr[0] = 0;
}

// ---------------------------------------------------------------------------
// Launch 3: scatter (src, edge_id) into dst-sorted order — 8 bytes per edge
// ---------------------------------------------------------------------------
__global__ void scatter_kernel(int E_) {
    int e = blockIdx.x * blockDim.x + threadIdx.x;
    if (e >= E_) return;
    int d = g_dst[e];
    int pos = g_rowptr[d] + atomicAdd(&g_cur[d], 1);
    g_se[pos] = make_int2(g_src[e], e);
}

// ---------------------------------------------------------------------------
// Gather: one warp per 64 channels of a node.
//   D=64 : 1 warp/node.  D=128 : 2 warps/node (disjoint channel halves).
// ea rows: 2-stage cp.async ring in smem (1 chunk ahead, covers DRAM lat),
// broadcast LDS.128 in compute.
// x rows: REGISTER-ROTATED one chunk ahead — in the unrolled compute of
// chunk c, xv[j] is consumed then immediately reloaded (LDG.64, coalesced)
// for chunk c+1. Cover = rest of compute(c) + ea-wait(c+1) >= L2 latency.
// No smem round-trip for x: ~47% fewer L1 wavefronts vs staged version.
//   h[n] = x[n] + sum_e relu( x[src_e] + ea_e @ We + be )
// ---------------------------------------------------------------------------
template <int D>
__global__ void __launch_bounds__(256, 3) gather_kernel(
    const float* __restrict__ xp, int xs, const float* __restrict__ ea,
    const float* __restrict__ We, const float* __restrict__ be, int N_)
{
    constexpr int WPN = D / 64;
    __shared__ __align__(16) float s_ea[8][2][8][16];   // [warp][stage][edge][k]

    const float* __restrict__ x = xp ? xp : (xs == 0 ? g_hA : g_hB);
    int w = threadIdx.x >> 5;
    int lane = threadIdx.x & 31;
    int gw = blockIdx.x * 8 + w;
    int n = gw / WPN;
    if (n >= N_) return;
    int half = gw - n * WPN;
    int ch0 = half * 64 + lane * 2;

    // K-pair-packed weights for this lane's 2 channels (32 regs)
    u64 wp0[8], wp1[8];
    #pragma unroll
    for (int k2 = 0; k2 < 8; k2++) {
        wp0[k2] = pack2(We[(2 * k2) * D + ch0],     We[(2 * k2 + 1) * D + ch0]);
        wp1[k2] = pack2(We[(2 * k2) * D + ch0 + 1], We[(2 * k2 + 1) * D + ch0 + 1]);
    }
    float b0 = be[ch0], b1 = be[ch0 + 1];

    int beg = g_rowptr[n];
    int end = g_rowptr[n + 1];
    float a0 = 0.f, a1 = 0.f;
    int nch = (end - beg + 7) >> 3;

    unsigned sea_b = (unsigned)__cvta_generic_to_shared(&s_ea[w][0][0][0]);
    int jr = lane >> 2, q4 = lane & 3;   // ea staging: 1 float4 per lane
    int j8 = lane & 7;
    const float* __restrict__ xl = x + ch0;   // per-lane channel base

    auto issue_ea = [&](int st, int eidreg) {
        int eid = __shfl_sync(0xFFFFFFFFu, eidreg, jr);
        cp_async16s(sea_b + st * 512 + jr * 64 + q4 * 16,
                    ea + (size_t)eid * 16 + q4 * 4);
        cp_commit();
    };

    // FFMA2 chain for one edge: xv + bias folded into accumulator init
    auto edge_math = [&](float2 xv, const ulonglong2* er2) {
        ulonglong2 u0 = er2[0], u1 = er2[1], u2 = er2[2], u3 = er2[3];
        u64 s0 = pack2(b0, xv.x);
        u64 s1 = pack2(b1, xv.y);
        s0 = ffma2(u0.x, wp0[0], s0); s1 = ffma2(u0.x, wp1[0], s1);
        s0 = ffma2(u0.y, wp0[1], s0); s1 = ffma2(u0.y, wp1[1], s1);
        s0 = ffma2(u1.x, wp0[2], s0); s1 = ffma2(u1.x, wp1[2], s1);
        s0 = ffma2(u1.y, wp0[3], s0); s1 = ffma2(u1.y, wp1[3], s1);
        s0 = ffma2(u2.x, wp0[4], s0); s1 = ffma2(u2.x, wp1[4], s1);
        s0 = ffma2(u2.y, wp0[5], s0); s1 = ffma2(u2.y, wp1[5], s1);
        s0 = ffma2(u3.x, wp0[6], s0); s1 = ffma2(u3.x, wp1[6], s1);
        s0 = ffma2(u3.y, wp0[7], s0); s1 = ffma2(u3.y, wp1[7], s1);
        float l0, h0, l1, h1;
        unpack2(s0, l0, h0);
        unpack2(s1, l1, h1);
        a0 += fmaxf(l0 + h0, 0.f);
        a1 += fmaxf(l1 + h1, 0.f);
    };

    if (nch > 0) {
        int2 p_cur = g_se[beg + j8];                 // unclamped (padded array)
        issue_ea(0, p_cur.y);
        // x prefetch for chunk 0 (covered by the DRAM ea-wait below)
        float2 xv[8];
        #pragma unroll
        for (int j = 0; j < 8; j++) {
            int src = __shfl_sync(0xFFFFFFFFu, p_cur.x, j);
            xv[j] = *(const float2*)(xl + (size_t)src * D);
        }
        int2 p_nxt = g_se[beg + 8 + j8];             // padded: safe even if unused

        int ecur = beg;
        for (int c = 0; c < nch; c++) {
            cp_wait<0>();        // ea chunk c arrived
            __syncwarp();        // staged ea visible; all lanes past compute(c-1)
            if (c + 1 < nch) issue_ea((c + 1) & 1, p_nxt.y);
            int2 p_fut = g_se[ecur + 16 + j8];       // lookahead (padded)

            int st = c & 1;
            const ulonglong2* ser = (const ulonglong2*)&s_ea[w][st][0][0];
            int cnt = end - ecur;
            if (cnt >= 8) {
                #pragma unroll
                for (int j = 0; j < 8; j++) {
                    float2 xcur = xv[j];
                    int srcn = __shfl_sync(0xFFFFFFFFu, p_nxt.x, j);
                    xv[j] = *(const float2*)(xl + (size_t)srcn * D);  // prefetch c+1
                    edge_math(xcur, ser + j * 4);
                }
            } else {
                for (int j = 0; j < cnt; j++) edge_math(xv[j], ser + j * 4);
            }
            p_nxt = p_fut;
            ecur += 8;
        }
    }

    float2 xn = *(const float2*)(xl + (size_t)n * D);
    *(float2*)(g_h + (size_t)n * D + ch0) = make_float2(a0 + xn.x, a1 + xn.y);
}

// ---------------------------------------------------------------------------
// Fused MLP kernel (persistent blocks; K-pair-packed weights in smem, FFMA2,
// LDS.128 A-operand loads)
// ---------------------------------------------------------------------------
template <int DIN>
__global__ void __launch_bounds__(256, 1) mlp_kernel(
    int os,
    const float* __restrict__ W1, const float* __restrict__ b1,
    const float* __restrict__ W2, const float* __restrict__ b2, int N_)
{
    extern __shared__ u64 smu[];
    u64* sW1p = smu;                         // (DIN/2)*128 u64
    u64* sW2p = sW1p + (DIN / 2) * 128;      // 64*128 u64
    float* sb1 = (float*)(sW2p + 64 * 128);  // 128
    float* sb2 = sb1 + 128;                  // 128
    float* sH  = sb2 + 128;                  // 64*DIN
    float* sT  = sH + 64 * DIN;              // 64*128

    int tid = threadIdx.x;
    for (int i = tid; i < (DIN / 2) * 128; i += 256) {
        int k2 = i >> 7, c = i & 127;
        sW1p[i] = pack2(W1[(2 * k2) * 128 + c], W1[(2 * k2 + 1) * 128 + c]);
    }
    for (int i = tid; i < 64 * 128; i += 256) {
        int k2 = i >> 7, c = i & 127;
        sW2p[i] = pack2(W2[(2 * k2) * 128 + c], W2[(2 * k2 + 1) * 128 + c]);
    }
    if (tid < 128) { sb1[tid] = b1[tid]; sb2[tid] = b2[tid]; }
    __syncthreads();

    float* outp = (os == 0) ? g_hA : g_hB;

    int tx = tid & 31;
    int ty = tid >> 5;

    const int ntiles = (N_ + 63) / 64;
    for (int tile = blockIdx.x; tile < ntiles; tile += gridDim.x) {
        int base = tile * 64;

        constexpr int C4 = DIN / 4;
        for (int i4 = tid; i4 < 64 * C4; i4 += 256) {
            int r = i4 / C4;
            int c4 = i4 - r * C4;
            int gr = base + r;
            float4 v = make_float4(0.f, 0.f, 0.f, 0.f);
            if (gr < N_) v = ((const float4*)g_h)[(size_t)gr * C4 + c4];
            ((float4*)sH)[i4] = v;
        }
        __syncthreads();

        // phase 1: t = relu(h @ W1 + b1)
        {
            u64 acc[8][4];
            #pragma unroll
            for (int r = 0; r < 8; r++)
                #pragma unroll
                for (int j = 0; j < 4; j++) acc[r][j] = 0ULL;
            #pragma unroll 2
            for (int k4 = 0; k4 < DIN / 4; k4++) {
                int k2a = 2 * k4;
                const ulonglong2* wra = (const ulonglong2*)(sW1p + k2a * 128);
                const ulonglong2* wrb = (const ulonglong2*)(sW1p + (k2a + 1) * 128);
                ulonglong2 wa01 = wra[tx * 2], wa23 = wra[tx * 2 + 1];
                ulonglong2 wb01 = wrb[tx * 2], wb23 = wrb[tx * 2 + 1];
                u64 wA[4] = {wa01.x, wa01.y, wa23.x, wa23.y};
                u64 wB[4] = {wb01.x, wb01.y, wb23.x, wb23.y};
                ulonglong2 a2[8];
                #pragma unroll
                for (int r = 0; r < 8; r++)
                    a2[r] = *(const ulonglong2*)(sH + (ty * 8 + r) * DIN + 4 * k4);
                #pragma unroll
                for (int r = 0; r < 8; r++)
                    #pragma unroll
                    for (int j = 0; j < 4; j++) {
                        acc[r][j] = ffma2(a2[r].x, wA[j], acc[r][j]);
                        acc[r][j] = ffma2(a2[r].y, wB[j], acc[r][j]);
                    }
            }
            float bb[4];
            #pragma unroll
            for (int j = 0; j < 4; j++) bb[j] = sb1[tx * 4 + j];
            #pragma unroll
            for (int r = 0; r < 8; r++) {
                float v[4];
                #pragma unroll
                for (int j = 0; j < 4; j++) {
                    float lo, hi;
                    unpack2(acc[r][j], lo, hi);
                    v[j] = fmaxf(lo + hi + bb[j], 0.f);
                }
                ((float4*)(sT + (ty * 8 + r) * 128))[tx] =
                    make_float4(v[0], v[1], v[2], v[3]);
            }
        }
        __syncthreads();

        // phase 2: out = relu(t @ W2 + b2)
        {
            u64 acc[8][4];
            #pragma unroll
            for (int r = 0; r < 8; r++)
                #pragma unroll
                for (int j = 0; j < 4; j++) acc[r][j] = 0ULL;
            #pragma unroll 2
            for (int k4 = 0; k4 < 32; k4++) {
                int k2a = 2 * k4;
                const ulonglong2* wra = (const ulonglong2*)(sW2p + k2a * 128);
                const ulonglong2* wrb = (const ulonglong2*)(sW2p + (k2a + 1) * 128);
                ulonglong2 wa01 = wra[tx * 2], wa23 = wra[tx * 2 + 1];
                ulonglong2 wb01 = wrb[tx * 2], wb23 = wrb[tx * 2 + 1];
                u64 wA[4] = {wa01.x, wa01.y, wa23.x, wa23.y};
                u64 wB[4] = {wb01.x, wb01.y, wb23.x, wb23.y};
                ulonglong2 a2[8];
                #pragma unroll
                for (int r = 0; r < 8; r++)
                    a2[r] = *(const ulonglong2*)(sT + (ty * 8 + r) * 128 + 4 * k4);
                #pragma unroll
                for (int r = 0; r < 8; r++)
                    #pragma unroll
                    for (int j = 0; j < 4; j++) {
                        acc[r][j] = ffma2(a2[r].x, wA[j], acc[r][j]);
                        acc[r][j] = ffma2(a2[r].y, wB[j], acc[r][j]);
                    }
            }
            float bb[4];
            #pragma unroll
            for (int j = 0; j < 4; j++) bb[j] = sb2[tx * 4 + j];
            #pragma unroll
            for (int r = 0; r < 8; r++) {
                int gr = base + ty * 8 + r;
                if (gr < N_) {
                    float v[4];
                    #pragma unroll
                    for (int j = 0; j < 4; j++) {
                        float lo, hi;
                        unpack2(acc[r][j], lo, hi);
                        v[j] = fmaxf(lo + hi + bb[j], 0.f);
                    }
                    ((float4*)(outp + (size_t)gr * 128))[tx] =
                        make_float4(v[0], v[1], v[2], v[3]);
                }
            }
        }
        __syncthreads();
    }
}

// ---------------------------------------------------------------------------
// Final: out[n] = sigmoid(h[n].Wlin + blin); also restores g_deg/g_cur = 0.
// ---------------------------------------------------------------------------
__global__ void __launch_bounds__(256) final_kernel(
    int hs, const float* __restrict__ Wlin, const float* __restrict__ blin,
    float* __restrict__ out, int N_)
{
    __shared__ float sw[128];
    if (threadIdx.x < 128) sw[threadIdx.x] = Wlin[threadIdx.x];
    __syncthreads();
    const float* h = (hs == 0) ? g_hA : g_hB;
    int lane = threadIdx.x & 31;
    int gtid = blockIdx.x * 256 + threadIdx.x;
    int warp = gtid >> 5;
    int nw = (gridDim.x * 256) >> 5;
    float bl = blin[0];
    for (int n = warp; n < N_; n += nw) {
        float4 hv = ((const float4*)(h + (size_t)n * 128))[lane];
        float4 wv = ((const float4*)sw)[lane];
        float v = hv.x * wv.x + hv.y * wv.y + hv.z * wv.z + hv.w * wv.w;
        #pragma unroll
        for (int o = 16; o; o >>= 1) v += __shfl_xor_sync(0xFFFFFFFFu, v, o);
        if (lane == 0) out[n] = 1.f / (1.f + expf(-(v + bl)));
    }
    if (gtid < N_) { g_deg[gtid] = 0; g_cur[gtid] = 0; }
}

// ---------------------------------------------------------------------------
extern "C" void kernel_launch(void* const* d_in, const int* in_sizes, int n_in,
                              void* d_out, int out_size)
{
    const float* x   = (const float*)d_in[0];
    const void*  ei  = d_in[1];
    const float* ea  = (const float*)d_in[2];
    const float* We0 = (const float*)d_in[3];
    const float* be0 = (const float*)d_in[4];
    const float* W10 = (const float*)d_in[5];
    const float* b10 = (const float*)d_in[6];
    const float* W20 = (const float*)d_in[7];
    const float* b20 = (const float*)d_in[8];
    const float* We1 = (const float*)d_in[9];
    const float* be1 = (const float*)d_in[10];
    const float* W11 = (const float*)d_in[11];
    const float* b11 = (const float*)d_in[12];
    const float* W21 = (const float*)d_in[13];
    const float* b21 = (const float*)d_in[14];
    const float* We2 = (const float*)d_in[15];
    const float* be2 = (const float*)d_in[16];
    const float* W12 = (const float*)d_in[17];
    const float* b12 = (const float*)d_in[18];
    const float* W22 = (const float*)d_in[19];
    const float* b22 = (const float*)d_in[20];
    const float* Wln = (const float*)d_in[21];
    const float* bln = (const float*)d_in[22];

    int N_ = in_sizes[0] / 64;
    int E_ = in_sizes[2] / 16;

    constexpr int SMEM64  = (32 * 128 + 64 * 128) * 8 + (256 + 64 * 64 + 64 * 128) * 4;
    constexpr int SMEM128 = (64 * 128 + 64 * 128) * 8 + (256 + 64 * 128 + 64 * 128) * 4;
    cudaFuncSetAttribute(mlp_kernel<64>,  cudaFuncAttributeMaxDynamicSharedMemorySize, SMEM64);
    cudaFuncSetAttribute(mlp_kernel<128>, cudaFuncAttributeMaxDynamicSharedMemorySize, SMEM128);

    int ebc = (E_ + 255) / 256;
    int gb64  = (N_ * 1 + 7) / 8;     // 1 warp/node, 8 warps/block
    int gb128 = (N_ * 2 + 7) / 8;     // 2 warps/node

    // ---- CSR build ----
    convert_hist_kernel<<<ebc, 256>>>(ei, E_, N_);      // launch 1
    scan_kernel<<<1, 1024>>>(N_);                       // launch 2
    scatter_kernel<<<ebc, 256>>>(E_);                   // launch 3

    // ---- layer 0 (d = 64) ----
    gather_kernel<64><<<gb64, 256>>>(x, 0, ea, We0, be0, N_);       // launch 4
    mlp_kernel<64><<<148, 256, SMEM64>>>(0, W10, b10, W20, b20, N_);

    // ---- layer 1 (d = 128) ----
    gather_kernel<128><<<gb128, 256>>>(nullptr, 0, ea, We1, be1, N_);
    mlp_kernel<128><<<148, 256, SMEM128>>>(1, W11, b11, W21, b21, N_);

    // ---- layer 2 (d = 128) ----
    gather_kernel<128><<<gb128, 256>>>(nullptr, 1, ea, We2, be2, N_);
    mlp_kernel<128><<<148, 256, SMEM128>>>(0, W12, b12, W22, b22, N_);

    // ---- final linear + sigmoid (+ restore zero-invariant) ----
    final_kernel<<<(N_ + 7) / 8, 256>>>(0, Wln, bln, (float*)d_out, N_);
}

// round 13
// speedup vs baseline: 1.1137x; 1.1137x over previous
#include <cuda_runtime.h>
#include <cstdint>

#define MAXN 50000
#define MAXE 1600000

// ---- scratch (static device globals: allocation-free) ----
// INVARIANT: g_deg/g_cur are zero at every kernel_launch entry (statically
// zero-initialized; final_kernel re-zeros them at the end of each call).
// g_se is padded by 32 entries (always zero => src 0 / edge 0: valid reads)
// so gather lookahead loads need no clamping.
__device__ float g_h [MAXN * 128];
__device__ float g_hA[MAXN * 128];
__device__ float g_hB[MAXN * 128];
__device__ int   g_deg[MAXN];
__device__ int   g_cur[MAXN];
__device__ int   g_rowptr[MAXN + 1];
__device__ int   g_src[MAXE];
__device__ int   g_dst[MAXE];
__device__ int2  g_se[MAXE + 32];   // (src, edge_id) sorted by dst, padded

// ---- packed f32x2 helpers ----
typedef unsigned long long u64;

__device__ __forceinline__ u64 pack2(float lo, float hi) {
    u64 r;
    asm("mov.b64 %0, {%1, %2};" : "=l"(r) : "f"(lo), "f"(hi));
    return r;
}
__device__ __forceinline__ void unpack2(u64 v, float& lo, float& hi) {
    asm("mov.b64 {%0, %1}, %2;" : "=f"(lo), "=f"(hi) : "l"(v));
}
__device__ __forceinline__ u64 ffma2(u64 a, u64 b, u64 c) {
    u64 d;
    asm("fma.rn.f32x2 %0, %1, %2, %3;" : "=l"(d) : "l"(a), "l"(b), "l"(c));
    return d;
}

// ---- cp.async helpers (smem address precomputed as u32) ----
__device__ __forceinline__ void cp_async16s(unsigned sdst, const void* src) {
    asm volatile("cp.async.cg.shared.global [%0], [%1], 16;" :: "r"(sdst), "l"(src));
}
__device__ __forceinline__ void cp_commit() {
    asm volatile("cp.async.commit_group;");
}
template <int N> __device__ __forceinline__ void cp_wait() {
    asm volatile("cp.async.wait_group %0;" :: "n"(N));
}

// ---------------------------------------------------------------------------
// Launch 1: convert edge_index to int32 (+dtype sniff per block) + dst histogram
// ---------------------------------------------------------------------------
__global__ void convert_hist_kernel(const void* __restrict__ ei, int E_, int N_) {
    __shared__ int bad;
    if (threadIdx.x == 0) bad = 0;
    __syncthreads();
    const long long* p64 = (const long long*)ei;
    int cnt = 0;
    for (int i = threadIdx.x; i < 512; i += blockDim.x) {
        long long v = p64[i];
        if (v < 0 || v >= (long long)N_) cnt++;
    }
    if (cnt) atomicAdd(&bad, cnt);
    __syncthreads();
    bool is64 = (bad < 256);

    int e = blockIdx.x * blockDim.x + threadIdx.x;
    if (e >= E_) return;
    int s, d;
    if (is64) {
        s = (int)p64[e]; d = (int)p64[E_ + e];
    } else {
        const int* p = (const int*)ei;
        s = p[e]; d = p[E_ + e];
    }
    g_src[e] = s;
    g_dst[e] = d;
    atomicAdd(&g_deg[d], 1);
}

// ---------------------------------------------------------------------------
// Launch 2: single-block exclusive scan of g_deg -> g_rowptr
// ---------------------------------------------------------------------------
__global__ void __launch_bounds__(1024) scan_kernel(int N_) {
    __shared__ int sh[1024];
    int tid = threadIdx.x;
    int chunk = (N_ + 1023) / 1024;
    int lo = tid * chunk;
    int hi = min(lo + chunk, N_);

    int sum = 0;
    for (int i = lo; i < hi; i++) sum += g_deg[i];
    sh[tid] = sum;
    __syncthreads();
    #pragma unroll
    for (int off = 1; off < 1024; off <<= 1) {
        int t = (tid >= off) ? sh[tid - off] : 0;
        __syncthreads();
        sh[tid] += t;
        __syncthreads();
    }
    int run = (tid > 0) ? sh[tid - 1] : 0;
    for (int i = lo; i < hi; i++) {
        run += g_deg[i];
        g_rowptr[i + 1] = run;
    }
    if (tid == 0) g_rowptr[0] = 0;
}

// ---------------------------------------------------------------------------
// Launch 3: scatter (src, edge_id) into dst-sorted order — 8 bytes per edge
// ---------------------------------------------------------------------------
__global__ void scatter_kernel(int E_) {
    int e = blockIdx.x * blockDim.x + threadIdx.x;
    if (e >= E_) return;
    int d = g_dst[e];
    int pos = g_rowptr[d] + atomicAdd(&g_cur[d], 1);
    g_se[pos] = make_int2(g_src[e], e);
}

// ---------------------------------------------------------------------------
// Gather: one warp per 64 channels of a node (R10 exact — best measured).
//   D=64 : 1 warp/node.  D=128 : 2 warps/node (disjoint channel halves).
// Per 8-edge chunk: ea row staged via cp.async 2-stage ring (1 chunk ahead,
// DRAM), x half-rows staged via cp.async in the same group (L2). Compute
// reads ea via broadcast LDS.128 and x via LDS.64; bias + x_src folded into
// the FFMA2 accumulator init. Lookahead g_se loads are unclamped (padded).
//   h[n] = x[n] + sum_e relu( x[src_e] + ea_e @ We + be )
// ---------------------------------------------------------------------------
template <int D>
__global__ void __launch_bounds__(256, 4) gather_kernel(
    const float* __restrict__ xp, int xs, const float* __restrict__ ea,
    const float* __restrict__ We, const float* __restrict__ be, int N_)
{
    constexpr int WPN = D / 64;
    __shared__ __align__(16) float s_ea[8][2][8][16];   // [warp][stage][edge][k]
    __shared__ __align__(16) float s_x [8][2][8][64];   // [warp][stage][edge][ch]

    const float* __restrict__ x = xp ? xp : (xs == 0 ? g_hA : g_hB);
    int w = threadIdx.x >> 5;
    int lane = threadIdx.x & 31;
    int gw = blockIdx.x * 8 + w;
    int n = gw / WPN;
    if (n >= N_) return;
    int half = gw - n * WPN;
    int chbase = half * 64;
    int ch0 = chbase + lane * 2;

    // K-pair-packed weights for this lane's 2 channels (32 regs)
    u64 wp0[8], wp1[8];
    #pragma unroll
    for (int k2 = 0; k2 < 8; k2++) {
        wp0[k2] = pack2(We[(2 * k2) * D + ch0],     We[(2 * k2 + 1) * D + ch0]);
        wp1[k2] = pack2(We[(2 * k2) * D + ch0 + 1], We[(2 * k2 + 1) * D + ch0 + 1]);
    }
    float b0 = be[ch0], b1 = be[ch0 + 1];

    int beg = g_rowptr[n];
    int end = g_rowptr[n + 1];
    float a0 = 0.f, a1 = 0.f;
    int nch = (end - beg + 7) >> 3;

    unsigned sea_b = (unsigned)__cvta_generic_to_shared(&s_ea[w][0][0][0]);
    unsigned sx_b  = (unsigned)__cvta_generic_to_shared(&s_x [w][0][0][0]);
    int jr = lane >> 2, q4 = lane & 3;       // ea: 1 float4 per lane
    int jx = lane >> 4, qx = lane & 15;      // x : 4 float4 per lane
    int j8 = lane & 7;

    auto issue_chunk = [&](int st, int2 pr) {
        int eid = __shfl_sync(0xFFFFFFFFu, pr.y, jr);
        cp_async16s(sea_b + st * 512 + jr * 64 + q4 * 16,
                    ea + (size_t)eid * 16 + q4 * 4);
        #pragma unroll
        for (int t = 0; t < 4; t++) {
            int j = jx + t * 2;
            int src = __shfl_sync(0xFFFFFFFFu, pr.x, j);
            cp_async16s(sx_b + st * 2048 + j * 256 + qx * 16,
                        x + (size_t)src * D + chbase + qx * 4);
        }
        cp_commit();
    };

    if (nch > 0) {
        int2 p_cur = g_se[beg + j8];                 // unclamped (padded array)
        issue_chunk(0, p_cur);
        int2 p_nxt = make_int2(0, 0);
        if (nch > 1) p_nxt = g_se[beg + 8 + j8];

        for (int c = 0; c < nch; c++) {
            if (c + 1 < nch) issue_chunk((c + 1) & 1, p_nxt);
            int2 p_fut = make_int2(0, 0);
            if (c + 2 < nch) p_fut = g_se[beg + (c + 2) * 8 + j8];
            if (c + 1 < nch) cp_wait<1>(); else cp_wait<0>();
            __syncwarp();

            int cnt = min(8, end - (beg + c * 8));
            int st = c & 1;
            for (int j = 0; j < cnt; j++) {
                float2 xv = *(const float2*)&s_x[w][st][j][lane * 2];
                const ulonglong2* er2 = (const ulonglong2*)s_ea[w][st][j];
                ulonglong2 u0 = er2[0], u1 = er2[1], u2 = er2[2], u3 = er2[3];
                u64 s0 = pack2(b0, xv.x);   // bias/x folded into accumulator
                u64 s1 = pack2(b1, xv.y);
                s0 = ffma2(u0.x, wp0[0], s0); s1 = ffma2(u0.x, wp1[0], s1);
                s0 = ffma2(u0.y, wp0[1], s0); s1 = ffma2(u0.y, wp1[1], s1);
                s0 = ffma2(u1.x, wp0[2], s0); s1 = ffma2(u1.x, wp1[2], s1);
                s0 = ffma2(u1.y, wp0[3], s0); s1 = ffma2(u1.y, wp1[3], s1);
                s0 = ffma2(u2.x, wp0[4], s0); s1 = ffma2(u2.x, wp1[4], s1);
                s0 = ffma2(u2.y, wp0[5], s0); s1 = ffma2(u2.y, wp1[5], s1);
                s0 = ffma2(u3.x, wp0[6], s0); s1 = ffma2(u3.x, wp1[6], s1);
                s0 = ffma2(u3.y, wp0[7], s0); s1 = ffma2(u3.y, wp1[7], s1);
                float l0, h0, l1, h1;
                unpack2(s0, l0, h0);
                unpack2(s1, l1, h1);
                a0 += fmaxf(l0 + h0, 0.f);
                a1 += fmaxf(l1 + h1, 0.f);
            }
            p_cur = p_nxt;
            p_nxt = p_fut;
            __syncwarp();   // all lanes done with stage st before it is reissued
        }
    }

    float2 xn = *(const float2*)(x + (size_t)n * D + ch0);
    *(float2*)(g_h + (size_t)n * D + ch0) = make_float2(a0 + xn.x, a1 + xn.y);
}

// ---------------------------------------------------------------------------
// Fused MLP kernel — 512 threads (16 warps/SM), persistent blocks;
// K-pair-packed weights in smem, FFMA2, LDS.128 A-operand loads.
// Each thread computes 4 rows x 4 cols of a 64-row tile.
// ---------------------------------------------------------------------------
template <int DIN>
__global__ void __launch_bounds__(512, 1) mlp_kernel(
    int os,
    const float* __restrict__ W1, const float* __restrict__ b1,
    const float* __restrict__ W2, const float* __restrict__ b2, int N_)
{
    extern __shared__ u64 smu[];
    u64* sW1p = smu;                         // (DIN/2)*128 u64
    u64* sW2p = sW1p + (DIN / 2) * 128;      // 64*128 u64
    float* sb1 = (float*)(sW2p + 64 * 128);  // 128
    float* sb2 = sb1 + 128;                  // 128
    float* sH  = sb2 + 128;                  // 64*DIN
    float* sT  = sH + 64 * DIN;              // 64*128

    int tid = threadIdx.x;
    for (int i = tid; i < (DIN / 2) * 128; i += 512) {
        int k2 = i >> 7, c = i & 127;
        sW1p[i] = pack2(W1[(2 * k2) * 128 + c], W1[(2 * k2 + 1) * 128 + c]);
    }
    for (int i = tid; i < 64 * 128; i += 512) {
        int k2 = i >> 7, c = i & 127;
        sW2p[i] = pack2(W2[(2 * k2) * 128 + c], W2[(2 * k2 + 1) * 128 + c]);
    }
    if (tid < 128) { sb1[tid] = b1[tid]; sb2[tid] = b2[tid]; }
    __syncthreads();

    float* outp = (os == 0) ? g_hA : g_hB;

    int tx = tid & 31;   // col group: cols tx*4 .. tx*4+3
    int ty = tid >> 5;   // row group: rows ty*4 .. ty*4+3  (16 groups)

    const int ntiles = (N_ + 63) / 64;
    for (int tile = blockIdx.x; tile < ntiles; tile += gridDim.x) {
        int base = tile * 64;

        constexpr int C4 = DIN / 4;
        for (int i4 = tid; i4 < 64 * C4; i4 += 512) {
            int r = i4 / C4;
            int c4 = i4 - r * C4;
            int gr = base + r;
            float4 v = make_float4(0.f, 0.f, 0.f, 0.f);
            if (gr < N_) v = ((const float4*)g_h)[(size_t)gr * C4 + c4];
            ((float4*)sH)[i4] = v;
        }
        __syncthreads();

        // phase 1: t = relu(h @ W1 + b1)
        {
            u64 acc[4][4];
            #pragma unroll
            for (int r = 0; r < 4; r++)
                #pragma unroll
                for (int j = 0; j < 4; j++) acc[r][j] = 0ULL;
            #pragma unroll 2
            for (int k4 = 0; k4 < DIN / 4; k4++) {
                int k2a = 2 * k4;
                const ulonglong2* wra = (const ulonglong2*)(sW1p + k2a * 128);
                const ulonglong2* wrb = (const ulonglong2*)(sW1p + (k2a + 1) * 128);
                ulonglong2 wa01 = wra[tx * 2], wa23 = wra[tx * 2 + 1];
                ulonglong2 wb01 = wrb[tx * 2], wb23 = wrb[tx * 2 + 1];
                u64 wA[4] = {wa01.x, wa01.y, wa23.x, wa23.y};
                u64 wB[4] = {wb01.x, wb01.y, wb23.x, wb23.y};
                ulonglong2 a2[4];
                #pragma unroll
                for (int r = 0; r < 4; r++)
                    a2[r] = *(const ulonglong2*)(sH + (ty * 4 + r) * DIN + 4 * k4);
                #pragma unroll
                for (int r = 0; r < 4; r++)
                    #pragma unroll
                    for (int j = 0; j < 4; j++) {
                        acc[r][j] = ffma2(a2[r].x, wA[j], acc[r][j]);
                        acc[r][j] = ffma2(a2[r].y, wB[j], acc[r][j]);
                    }
            }
            float bb[4];
            #pragma unroll
            for (int j = 0; j < 4; j++) bb[j] = sb1[tx * 4 + j];
            #pragma unroll
            for (int r = 0; r < 4; r++) {
                float v[4];
                #pragma unroll
                for (int j = 0; j < 4; j++) {
                    float lo, hi;
                    unpack2(acc[r][j], lo, hi);
                    v[j] = fmaxf(lo + hi + bb[j], 0.f);
                }
                ((float4*)(sT + (ty * 4 + r) * 128))[tx] =
                    make_float4(v[0], v[1], v[2], v[3]);
            }
        }
        __syncthreads();

        // phase 2: out = relu(t @ W2 + b2)
        {
            u64 acc[4][4];
            #pragma unroll
            for (int r = 0; r < 4; r++)
                #pragma unroll
                for (int j = 0; j < 4; j++) acc[r][j] = 0ULL;
            #pragma unroll 2
            for (int k4 = 0; k4 < 32; k4++) {
                int k2a = 2 * k4;
                const ulonglong2* wra = (const ulonglong2*)(sW2p + k2a * 128);
                const ulonglong2* wrb = (const ulonglong2*)(sW2p + (k2a + 1) * 128);
                ulonglong2 wa01 = wra[tx * 2], wa23 = wra[tx * 2 + 1];
                ulonglong2 wb01 = wrb[tx * 2], wb23 = wrb[tx * 2 + 1];
                u64 wA[4] = {wa01.x, wa01.y, wa23.x, wa23.y};
                u64 wB[4] = {wb01.x, wb01.y, wb23.x, wb23.y};
                ulonglong2 a2[4];
                #pragma unroll
                for (int r = 0; r < 4; r++)
                    a2[r] = *(const ulonglong2*)(sT + (ty * 4 + r) * 128 + 4 * k4);
                #pragma unroll
                for (int r = 0; r < 4; r++)
                    #pragma unroll
                    for (int j = 0; j < 4; j++) {
                        acc[r][j] = ffma2(a2[r].x, wA[j], acc[r][j]);
                        acc[r][j] = ffma2(a2[r].y, wB[j], acc[r][j]);
                    }
            }
            float bb[4];
            #pragma unroll
            for (int j = 0; j < 4; j++) bb[j] = sb2[tx * 4 + j];
            #pragma unroll
            for (int r = 0; r < 4; r++) {
                int gr = base + ty * 4 + r;
                if (gr < N_) {
                    float v[4];
                    #pragma unroll
                    for (int j = 0; j < 4; j++) {
                        float lo, hi;
                        unpack2(acc[r][j], lo, hi);
                        v[j] = fmaxf(lo + hi + bb[j], 0.f);
                    }
                    ((float4*)(outp + (size_t)gr * 128))[tx] =
                        make_float4(v[0], v[1], v[2], v[3]);
                }
            }
        }
        __syncthreads();
    }
}

// ---------------------------------------------------------------------------
// Final: out[n] = sigmoid(h[n].Wlin + blin); also restores g_deg/g_cur = 0.
// ---------------------------------------------------------------------------
__global__ void __launch_bounds__(256) final_kernel(
    int hs, const float* __restrict__ Wlin, const float* __restrict__ blin,
    float* __restrict__ out, int N_)
{
    __shared__ float sw[128];
    if (threadIdx.x < 128) sw[threadIdx.x] = Wlin[threadIdx.x];
    __syncthreads();
    const float* h = (hs == 0) ? g_hA : g_hB;
    int lane = threadIdx.x & 31;
    int gtid = blockIdx.x * 256 + threadIdx.x;
    int warp = gtid >> 5;
    int nw = (gridDim.x * 256) >> 5;
    float bl = blin[0];
    for (int n = warp; n < N_; n += nw) {
        float4 hv = ((const float4*)(h + (size_t)n * 128))[lane];
        float4 wv = ((const float4*)sw)[lane];
        float v = hv.x * wv.x + hv.y * wv.y + hv.z * wv.z + hv.w * wv.w;
        #pragma unroll
        for (int o = 16; o; o >>= 1) v += __shfl_xor_sync(0xFFFFFFFFu, v, o);
        if (lane == 0) out[n] = 1.f / (1.f + expf(-(v + bl)));
    }
    if (gtid < N_) { g_deg[gtid] = 0; g_cur[gtid] = 0; }
}

// ---------------------------------------------------------------------------
extern "C" void kernel_launch(void* const* d_in, const int* in_sizes, int n_in,
                              void* d_out, int out_size)
{
    const float* x   = (const float*)d_in[0];
    const void*  ei  = d_in[1];
    const float* ea  = (const float*)d_in[2];
    const float* We0 = (const float*)d_in[3];
    const float* be0 = (const float*)d_in[4];
    const float* W10 = (const float*)d_in[5];
    const float* b10 = (const float*)d_in[6];
    const float* W20 = (const float*)d_in[7];
    const float* b20 = (const float*)d_in[8];
    const float* We1 = (const float*)d_in[9];
    const float* be1 = (const float*)d_in[10];
    const float* W11 = (const float*)d_in[11];
    const float* b11 = (const float*)d_in[12];
    const float* W21 = (const float*)d_in[13];
    const float* b21 = (const float*)d_in[14];
    const float* We2 = (const float*)d_in[15];
    const float* be2 = (const float*)d_in[16];
    const float* W12 = (const float*)d_in[17];
    const float* b12 = (const float*)d_in[18];
    const float* W22 = (const float*)d_in[19];
    const float* b22 = (const float*)d_in[20];
    const float* Wln = (const float*)d_in[21];
    const float* bln = (const float*)d_in[22];

    int N_ = in_sizes[0] / 64;
    int E_ = in_sizes[2] / 16;

    constexpr int SMEM64  = (32 * 128 + 64 * 128) * 8 + (256 + 64 * 64 + 64 * 128) * 4;
    constexpr int SMEM128 = (64 * 128 + 64 * 128) * 8 + (256 + 64 * 128 + 64 * 128) * 4;
    cudaFuncSetAttribute(mlp_kernel<64>,  cudaFuncAttributeMaxDynamicSharedMemorySize, SMEM64);
    cudaFuncSetAttribute(mlp_kernel<128>, cudaFuncAttributeMaxDynamicSharedMemorySize, SMEM128);

    int ebc = (E_ + 255) / 256;
    int gb64  = (N_ * 1 + 7) / 8;     // 1 warp/node, 8 warps/block
    int gb128 = (N_ * 2 + 7) / 8;     // 2 warps/node

    // ---- CSR build ----
    convert_hist_kernel<<<ebc, 256>>>(ei, E_, N_);      // launch 1
    scan_kernel<<<1, 1024>>>(N_);                       // launch 2
    scatter_kernel<<<ebc, 256>>>(E_);                   // launch 3

    // ---- layer 0 (d = 64) ----
    gather_kernel<64><<<gb64, 256>>>(x, 0, ea, We0, be0, N_);       // launch 4
    mlp_kernel<64><<<148, 512, SMEM64>>>(0, W10, b10, W20, b20, N_);

    // ---- layer 1 (d = 128) ----
    gather_kernel<128><<<gb128, 256>>>(nullptr, 0, ea, We1, be1, N_);
    mlp_kernel<128><<<148, 512, SMEM128>>>(1, W11, b11, W21, b21, N_);

    // ---- layer 2 (d = 128) ----
    gather_kernel<128><<<gb128, 256>>>(nullptr, 1, ea, We2, be2, N_);
    mlp_kernel<128><<<148, 512, SMEM128>>>(0, W12, b12, W22, b22, N_);

    // ---- final linear + sigmoid (+ restore zero-invariant) ----
    final_kernel<<<(N_ + 7) / 8, 256>>>(0, Wln, bln, (float*)d_out, N_);
}

// round 14
// speedup vs baseline: 1.2763x; 1.1461x over previous
#include <cuda_runtime.h>
#include <cstdint>

#define MAXN 50000
#define MAXE 1600000

// ---- scratch (static device globals: allocation-free) ----
// INVARIANT: g_deg/g_cur are zero at every kernel_launch entry (statically
// zero-initialized; final_kernel re-zeros them at the end of each call).
// g_se is padded by 32 entries (always zero => src 0 / edge 0: valid reads)
// so gather lookahead loads need no clamping.
__device__ float g_h [MAXN * 128];
__device__ float g_t [MAXN * 128];   // MLP hidden scratch (L2-resident)
__device__ float g_hA[MAXN * 128];
__device__ float g_hB[MAXN * 128];
__device__ int   g_deg[MAXN];
__device__ int   g_cur[MAXN];
__device__ int   g_rowptr[MAXN + 1];
__device__ int   g_src[MAXE];
__device__ int   g_dst[MAXE];
__device__ int2  g_se[MAXE + 32];   // (src, edge_id) sorted by dst, padded

// ---- packed f32x2 helpers ----
typedef unsigned long long u64;

__device__ __forceinline__ u64 pack2(float lo, float hi) {
    u64 r;
    asm("mov.b64 %0, {%1, %2};" : "=l"(r) : "f"(lo), "f"(hi));
    return r;
}
__device__ __forceinline__ void unpack2(u64 v, float& lo, float& hi) {
    asm("mov.b64 {%0, %1}, %2;" : "=f"(lo), "=f"(hi) : "l"(v));
}
__device__ __forceinline__ u64 ffma2(u64 a, u64 b, u64 c) {
    u64 d;
    asm("fma.rn.f32x2 %0, %1, %2, %3;" : "=l"(d) : "l"(a), "l"(b), "l"(c));
    return d;
}

// ---- cp.async helpers (smem address precomputed as u32) ----
__device__ __forceinline__ void cp_async16s(unsigned sdst, const void* src) {
    asm volatile("cp.async.cg.shared.global [%0], [%1], 16;" :: "r"(sdst), "l"(src));
}
__device__ __forceinline__ void cp_commit() {
    asm volatile("cp.async.commit_group;");
}
template <int N> __device__ __forceinline__ void cp_wait() {
    asm volatile("cp.async.wait_group %0;" :: "n"(N));
}

// ---------------------------------------------------------------------------
// Launch 1: convert edge_index to int32 (+dtype sniff per block) + dst histogram
// ---------------------------------------------------------------------------
__global__ void convert_hist_kernel(const void* __restrict__ ei, int E_, int N_) {
    __shared__ int bad;
    if (threadIdx.x == 0) bad = 0;
    __syncthreads();
    const long long* p64 = (const long long*)ei;
    int cnt = 0;
    for (int i = threadIdx.x; i < 512; i += blockDim.x) {
        long long v = p64[i];
        if (v < 0 || v >= (long long)N_) cnt++;
    }
    if (cnt) atomicAdd(&bad, cnt);
    __syncthreads();
    bool is64 = (bad < 256);

    int e = blockIdx.x * blockDim.x + threadIdx.x;
    if (e >= E_) return;
    int s, d;
    if (is64) {
        s = (int)p64[e]; d = (int)p64[E_ + e];
    } else {
        const int* p = (const int*)ei;
        s = p[e]; d = p[E_ + e];
    }
    g_src[e] = s;
    g_dst[e] = d;
    atomicAdd(&g_deg[d], 1);
}

// ---------------------------------------------------------------------------
// Launch 2: single-block exclusive scan of g_deg -> g_rowptr
// ---------------------------------------------------------------------------
__global__ void __launch_bounds__(1024) scan_kernel(int N_) {
    __shared__ int sh[1024];
    int tid = threadIdx.x;
    int chunk = (N_ + 1023) / 1024;
    int lo = tid * chunk;
    int hi = min(lo + chunk, N_);

    int sum = 0;
    for (int i = lo; i < hi; i++) sum += g_deg[i];
    sh[tid] = sum;
    __syncthreads();
    #pragma unroll
    for (int off = 1; off < 1024; off <<= 1) {
        int t = (tid >= off) ? sh[tid - off] : 0;
        __syncthreads();
        sh[tid] += t;
        __syncthreads();
    }
    int run = (tid > 0) ? sh[tid - 1] : 0;
    for (int i = lo; i < hi; i++) {
        run += g_deg[i];
        g_rowptr[i + 1] = run;
    }
    if (tid == 0) g_rowptr[0] = 0;
}

// ---------------------------------------------------------------------------
// Launch 3: scatter (src, edge_id) into dst-sorted order — 8 bytes per edge
// ---------------------------------------------------------------------------
__global__ void scatter_kernel(int E_) {
    int e = blockIdx.x * blockDim.x + threadIdx.x;
    if (e >= E_) return;
    int d = g_dst[e];
    int pos = g_rowptr[d] + atomicAdd(&g_cur[d], 1);
    g_se[pos] = make_int2(g_src[e], e);
}

// ---------------------------------------------------------------------------
// Gather: one warp per 64 channels of a node (R10 exact — best measured).
//   D=64 : 1 warp/node.  D=128 : 2 warps/node (disjoint channel halves).
// Per 8-edge chunk: ea row staged via cp.async 2-stage ring (1 chunk ahead,
// DRAM), x half-rows staged via cp.async in the same group (L2). Compute
// reads ea via broadcast LDS.128 and x via LDS.64; bias + x_src folded into
// the FFMA2 accumulator init. Lookahead g_se loads are unclamped (padded).
//   h[n] = x[n] + sum_e relu( x[src_e] + ea_e @ We + be )
// ---------------------------------------------------------------------------
template <int D>
__global__ void __launch_bounds__(256, 4) gather_kernel(
    const float* __restrict__ xp, int xs, const float* __restrict__ ea,
    const float* __restrict__ We, const float* __restrict__ be, int N_)
{
    constexpr int WPN = D / 64;
    __shared__ __align__(16) float s_ea[8][2][8][16];   // [warp][stage][edge][k]
    __shared__ __align__(16) float s_x [8][2][8][64];   // [warp][stage][edge][ch]

    const float* __restrict__ x = xp ? xp : (xs == 0 ? g_hA : g_hB);
    int w = threadIdx.x >> 5;
    int lane = threadIdx.x & 31;
    int gw = blockIdx.x * 8 + w;
    int n = gw / WPN;
    if (n >= N_) return;
    int half = gw - n * WPN;
    int chbase = half * 64;
    int ch0 = chbase + lane * 2;

    // K-pair-packed weights for this lane's 2 channels (32 regs)
    u64 wp0[8], wp1[8];
    #pragma unroll
    for (int k2 = 0; k2 < 8; k2++) {
        wp0[k2] = pack2(We[(2 * k2) * D + ch0],     We[(2 * k2 + 1) * D + ch0]);
        wp1[k2] = pack2(We[(2 * k2) * D + ch0 + 1], We[(2 * k2 + 1) * D + ch0 + 1]);
    }
    float b0 = be[ch0], b1 = be[ch0 + 1];

    int beg = g_rowptr[n];
    int end = g_rowptr[n + 1];
    float a0 = 0.f, a1 = 0.f;
    int nch = (end - beg + 7) >> 3;

    unsigned sea_b = (unsigned)__cvta_generic_to_shared(&s_ea[w][0][0][0]);
    unsigned sx_b  = (unsigned)__cvta_generic_to_shared(&s_x [w][0][0][0]);
    int jr = lane >> 2, q4 = lane & 3;       // ea: 1 float4 per lane
    int jx = lane >> 4, qx = lane & 15;      // x : 4 float4 per lane
    int j8 = lane & 7;

    auto issue_chunk = [&](int st, int2 pr) {
        int eid = __shfl_sync(0xFFFFFFFFu, pr.y, jr);
        cp_async16s(sea_b + st * 512 + jr * 64 + q4 * 16,
                    ea + (size_t)eid * 16 + q4 * 4);
        #pragma unroll
        for (int t = 0; t < 4; t++) {
            int j = jx + t * 2;
            int src = __shfl_sync(0xFFFFFFFFu, pr.x, j);
            cp_async16s(sx_b + st * 2048 + j * 256 + qx * 16,
                        x + (size_t)src * D + chbase + qx * 4);
        }
        cp_commit();
    };

    if (nch > 0) {
        int2 p_cur = g_se[beg + j8];                 // unclamped (padded array)
        issue_chunk(0, p_cur);
        int2 p_nxt = make_int2(0, 0);
        if (nch > 1) p_nxt = g_se[beg + 8 + j8];

        for (int c = 0; c < nch; c++) {
            if (c + 1 < nch) issue_chunk((c + 1) & 1, p_nxt);
            int2 p_fut = make_int2(0, 0);
            if (c + 2 < nch) p_fut = g_se[beg + (c + 2) * 8 + j8];
            if (c + 1 < nch) cp_wait<1>(); else cp_wait<0>();
            __syncwarp();

            int cnt = min(8, end - (beg + c * 8));
            int st = c & 1;
            for (int j = 0; j < cnt; j++) {
                float2 xv = *(const float2*)&s_x[w][st][j][lane * 2];
                const ulonglong2* er2 = (const ulonglong2*)s_ea[w][st][j];
                ulonglong2 u0 = er2[0], u1 = er2[1], u2 = er2[2], u3 = er2[3];
                u64 s0 = pack2(b0, xv.x);   // bias/x folded into accumulator
                u64 s1 = pack2(b1, xv.y);
                s0 = ffma2(u0.x, wp0[0], s0); s1 = ffma2(u0.x, wp1[0], s1);
                s0 = ffma2(u0.y, wp0[1], s0); s1 = ffma2(u0.y, wp1[1], s1);
                s0 = ffma2(u1.x, wp0[2], s0); s1 = ffma2(u1.x, wp1[2], s1);
                s0 = ffma2(u1.y, wp0[3], s0); s1 = ffma2(u1.y, wp1[3], s1);
                s0 = ffma2(u2.x, wp0[4], s0); s1 = ffma2(u2.x, wp1[4], s1);
                s0 = ffma2(u2.y, wp0[5], s0); s1 = ffma2(u2.y, wp1[5], s1);
                s0 = ffma2(u3.x, wp0[6], s0); s1 = ffma2(u3.x, wp1[6], s1);
                s0 = ffma2(u3.y, wp0[7], s0); s1 = ffma2(u3.y, wp1[7], s1);
                float l0, h0, l1, h1;
                unpack2(s0, l0, h0);
                unpack2(s1, l1, h1);
                a0 += fmaxf(l0 + h0, 0.f);
                a1 += fmaxf(l1 + h1, 0.f);
            }
            p_cur = p_nxt;
            p_nxt = p_fut;
            __syncwarp();   // all lanes done with stage st before it is reissued
        }
    }

    float2 xn = *(const float2*)(x + (size_t)n * D + ch0);
    *(float2*)(g_h + (size_t)n * D + ch0) = make_float2(a0 + xn.x, a1 + xn.y);
}

// ---------------------------------------------------------------------------
// MLP phase 1: t = relu(h @ W1 + b1)   (g_h -> g_t)
// 256 threads, 8 rows x 4 cols per thread (proven tile), but only W1 in smem
// -> 2 blocks/SM (16 warps) instead of the fused kernel's 1 block (8 warps).
// ---------------------------------------------------------------------------
template <int DIN>
__global__ void __launch_bounds__(256, 2) mlp1_kernel(
    const float* __restrict__ W1, const float* __restrict__ b1, int N_)
{
    extern __shared__ u64 smu[];
    u64* sWp = smu;                             // (DIN/2)*128 u64
    float* sb = (float*)(sWp + (DIN / 2) * 128);// 128
    float* sH = sb + 128;                       // 64*DIN

    int tid = threadIdx.x;
    for (int i = tid; i < (DIN / 2) * 128; i += 256) {
        int k2 = i >> 7, c = i & 127;
        sWp[i] = pack2(W1[(2 * k2) * 128 + c], W1[(2 * k2 + 1) * 128 + c]);
    }
    if (tid < 128) sb[tid] = b1[tid];
    __syncthreads();

    int tx = tid & 31;
    int ty = tid >> 5;

    const int ntiles = (N_ + 63) / 64;
    for (int tile = blockIdx.x; tile < ntiles; tile += gridDim.x) {
        int base = tile * 64;

        constexpr int C4 = DIN / 4;
        for (int i4 = tid; i4 < 64 * C4; i4 += 256) {
            int r = i4 / C4;
            int c4 = i4 - r * C4;
            int gr = base + r;
            float4 v = make_float4(0.f, 0.f, 0.f, 0.f);
            if (gr < N_) v = ((const float4*)g_h)[(size_t)gr * C4 + c4];
            ((float4*)sH)[i4] = v;
        }
        __syncthreads();

        u64 acc[8][4];
        #pragma unroll
        for (int r = 0; r < 8; r++)
            #pragma unroll
            for (int j = 0; j < 4; j++) acc[r][j] = 0ULL;
        #pragma unroll 2
        for (int k4 = 0; k4 < DIN / 4; k4++) {
            int k2a = 2 * k4;
            const ulonglong2* wra = (const ulonglong2*)(sWp + k2a * 128);
            const ulonglong2* wrb = (const ulonglong2*)(sWp + (k2a + 1) * 128);
            ulonglong2 wa01 = wra[tx * 2], wa23 = wra[tx * 2 + 1];
            ulonglong2 wb01 = wrb[tx * 2], wb23 = wrb[tx * 2 + 1];
            u64 wA[4] = {wa01.x, wa01.y, wa23.x, wa23.y};
            u64 wB[4] = {wb01.x, wb01.y, wb23.x, wb23.y};
            ulonglong2 a2[8];
            #pragma unroll
            for (int r = 0; r < 8; r++)
                a2[r] = *(const ulonglong2*)(sH + (ty * 8 + r) * DIN + 4 * k4);
            #pragma unroll
            for (int r = 0; r < 8; r++)
                #pragma unroll
                for (int j = 0; j < 4; j++) {
                    acc[r][j] = ffma2(a2[r].x, wA[j], acc[r][j]);
                    acc[r][j] = ffma2(a2[r].y, wB[j], acc[r][j]);
                }
        }
        float bb[4];
        #pragma unroll
        for (int j = 0; j < 4; j++) bb[j] = sb[tx * 4 + j];
        #pragma unroll
        for (int r = 0; r < 8; r++) {
            int gr = base + ty * 8 + r;
            if (gr < N_) {
                float v[4];
                #pragma unroll
                for (int j = 0; j < 4; j++) {
                    float lo, hi;
                    unpack2(acc[r][j], lo, hi);
                    v[j] = fmaxf(lo + hi + bb[j], 0.f);
                }
                ((float4*)(g_t + (size_t)gr * 128))[tx] =
                    make_float4(v[0], v[1], v[2], v[3]);
            }
        }
        __syncthreads();
    }
}

// ---------------------------------------------------------------------------
// MLP phase 2: out = relu(t @ W2 + b2)   (g_t -> g_hA/g_hB)
// ---------------------------------------------------------------------------
__global__ void __launch_bounds__(256, 2) mlp2_kernel(
    int os, const float* __restrict__ W2, const float* __restrict__ b2, int N_)
{
    extern __shared__ u64 smu[];
    u64* sWp = smu;                             // 64*128 u64
    float* sb = (float*)(sWp + 64 * 128);       // 128
    float* sT = sb + 128;                       // 64*128

    int tid = threadIdx.x;
    for (int i = tid; i < 64 * 128; i += 256) {
        int k2 = i >> 7, c = i & 127;
        sWp[i] = pack2(W2[(2 * k2) * 128 + c], W2[(2 * k2 + 1) * 128 + c]);
    }
    if (tid < 128) sb[tid] = b2[tid];
    __syncthreads();

    float* outp = (os == 0) ? g_hA : g_hB;
    int tx = tid & 31;
    int ty = tid >> 5;

    const int ntiles = (N_ + 63) / 64;
    for (int tile = blockIdx.x; tile < ntiles; tile += gridDim.x) {
        int base = tile * 64;

        for (int i4 = tid; i4 < 64 * 32; i4 += 256) {
            int r = i4 >> 5;
            int c4 = i4 & 31;
            int gr = base + r;
            float4 v = make_float4(0.f, 0.f, 0.f, 0.f);
            if (gr < N_) v = ((const float4*)g_t)[(size_t)gr * 32 + c4];
            ((float4*)sT)[i4] = v;
        }
        __syncthreads();

        u64 acc[8][4];
        #pragma unroll
        for (int r = 0; r < 8; r++)
            #pragma unroll
            for (int j = 0; j < 4; j++) acc[r][j] = 0ULL;
        #pragma unroll 2
        for (int k4 = 0; k4 < 32; k4++) {
            int k2a = 2 * k4;
            const ulonglong2* wra = (const ulonglong2*)(sWp + k2a * 128);
            const ulonglong2* wrb = (const ulonglong2*)(sWp + (k2a + 1) * 128);
            ulonglong2 wa01 = wra[tx * 2], wa23 = wra[tx * 2 + 1];
            ulonglong2 wb01 = wrb[tx * 2], wb23 = wrb[tx * 2 + 1];
            u64 wA[4] = {wa01.x, wa01.y, wa23.x, wa23.y};
            u64 wB[4] = {wb01.x, wb01.y, wb23.x, wb23.y};
            ulonglong2 a2[8];
            #pragma unroll
            for (int r = 0; r < 8; r++)
                a2[r] = *(const ulonglong2*)(sT + (ty * 8 + r) * 128 + 4 * k4);
            #pragma unroll
            for (int r = 0; r < 8; r++)
                #pragma unroll
                for (int j = 0; j < 4; j++) {
                    acc[r][j] = ffma2(a2[r].x, wA[j], acc[r][j]);
                    acc[r][j] = ffma2(a2[r].y, wB[j], acc[r][j]);
                }
        }
        float bb[4];
        #pragma unroll
        for (int j = 0; j < 4; j++) bb[j] = sb[tx * 4 + j];
        #pragma unroll
        for (int r = 0; r < 8; r++) {
            int gr = base + ty * 8 + r;
            if (gr < N_) {
                float v[4];
                #pragma unroll
                for (int j = 0; j < 4; j++) {
                    float lo, hi;
                    unpack2(acc[r][j], lo, hi);
                    v[j] = fmaxf(lo + hi + bb[j], 0.f);
                }
                ((float4*)(outp + (size_t)gr * 128))[tx] =
                    make_float4(v[0], v[1], v[2], v[3]);
            }
        }
        __syncthreads();
    }
}

// ---------------------------------------------------------------------------
// Final: out[n] = sigmoid(h[n].Wlin + blin); also restores g_deg/g_cur = 0.
// ---------------------------------------------------------------------------
__global__ void __launch_bounds__(256) final_kernel(
    int hs, const float* __restrict__ Wlin, const float* __restrict__ blin,
    float* __restrict__ out, int N_)
{
    __shared__ float sw[128];
    if (threadIdx.x < 128) sw[threadIdx.x] = Wlin[threadIdx.x];
    __syncthreads();
    const float* h = (hs == 0) ? g_hA : g_hB;
    int lane = threadIdx.x & 31;
    int gtid = blockIdx.x * 256 + threadIdx.x;
    int warp = gtid >> 5;
    int nw = (gridDim.x * 256) >> 5;
    float bl = blin[0];
    for (int n = warp; n < N_; n += nw) {
        float4 hv = ((const float4*)(h + (size_t)n * 128))[lane];
        float4 wv = ((const float4*)sw)[lane];
        float v = hv.x * wv.x + hv.y * wv.y + hv.z * wv.z + hv.w * wv.w;
        #pragma unroll
        for (int o = 16; o; o >>= 1) v += __shfl_xor_sync(0xFFFFFFFFu, v, o);
        if (lane == 0) out[n] = 1.f / (1.f + expf(-(v + bl)));
    }
    if (gtid < N_) { g_deg[gtid] = 0; g_cur[gtid] = 0; }
}

// ---------------------------------------------------------------------------
extern "C" void kernel_launch(void* const* d_in, const int* in_sizes, int n_in,
                              void* d_out, int out_size)
{
    const float* x   = (const float*)d_in[0];
    const void*  ei  = d_in[1];
    const float* ea  = (const float*)d_in[2];
    const float* We0 = (const float*)d_in[3];
    const float* be0 = (const float*)d_in[4];
    const float* W10 = (const float*)d_in[5];
    const float* b10 = (const float*)d_in[6];
    const float* W20 = (const float*)d_in[7];
    const float* b20 = (const float*)d_in[8];
    const float* We1 = (const float*)d_in[9];
    const float* be1 = (const float*)d_in[10];
    const float* W11 = (const float*)d_in[11];
    const float* b11 = (const float*)d_in[12];
    const float* W21 = (const float*)d_in[13];
    const float* b21 = (const float*)d_in[14];
    const float* We2 = (const float*)d_in[15];
    const float* be2 = (const float*)d_in[16];
    const float* W12 = (const float*)d_in[17];
    const float* b12 = (const float*)d_in[18];
    const float* W22 = (const float*)d_in[19];
    const float* b22 = (const float*)d_in[20];
    const float* Wln = (const float*)d_in[21];
    const float* bln = (const float*)d_in[22];

    int N_ = in_sizes[0] / 64;
    int E_ = in_sizes[2] / 16;

    constexpr int SM1_64  = (32 * 128) * 8 + 512 + (64 * 64) * 4;     // 49,664
    constexpr int SM1_128 = (64 * 128) * 8 + 512 + (64 * 128) * 4;    // 98,816
    constexpr int SM2     = (64 * 128) * 8 + 512 + (64 * 128) * 4;    // 98,816
    cudaFuncSetAttribute(mlp1_kernel<64>,  cudaFuncAttributeMaxDynamicSharedMemorySize, SM1_64);
    cudaFuncSetAttribute(mlp1_kernel<128>, cudaFuncAttributeMaxDynamicSharedMemorySize, SM1_128);
    cudaFuncSetAttribute(mlp2_kernel,      cudaFuncAttributeMaxDynamicSharedMemorySize, SM2);

    int ebc = (E_ + 255) / 256;
    int gb64  = (N_ * 1 + 7) / 8;     // 1 warp/node, 8 warps/block
    int gb128 = (N_ * 2 + 7) / 8;     // 2 warps/node
    const int MGRID = 296;            // 148 SMs x 2 blocks

    // ---- CSR build ----
    convert_hist_kernel<<<ebc, 256>>>(ei, E_, N_);      // launch 1
    scan_kernel<<<1, 1024>>>(N_);                       // launch 2
    scatter_kernel<<<ebc, 256>>>(E_);                   // launch 3

    // ---- layer 0 (d = 64) ----
    gather_kernel<64><<<gb64, 256>>>(x, 0, ea, We0, be0, N_);       // launch 4
    mlp1_kernel<64><<<MGRID, 256, SM1_64>>>(W10, b10, N_);
    mlp2_kernel<<<MGRID, 256, SM2>>>(0, W20, b20, N_);

    // ---- layer 1 (d = 128) ----
    gather_kernel<128><<<gb128, 256>>>(nullptr, 0, ea, We1, be1, N_);
    mlp1_kernel<128><<<MGRID, 256, SM1_128>>>(W11, b11, N_);
    mlp2_kernel<<<MGRID, 256, SM2>>>(1, W21, b21, N_);

    // ---- layer 2 (d = 128) ----
    gather_kernel<128><<<gb128, 256>>>(nullptr, 1, ea, We2, be2, N_);
    mlp1_kernel<128><<<MGRID, 256, SM1_128>>>(W12, b12, N_);
    mlp2_kernel<<<MGRID, 256, SM2>>>(0, W22, b22, N_);

    // ---- final linear + sigmoid (+ restore zero-invariant) ----
    final_kernel<<<(N_ + 7) / 8, 256>>>(0, Wln, bln, (float*)d_out, N_);
}

// round 15
// speedup vs baseline: 1.2823x; 1.0047x over previous
#include <cuda_runtime.h>
#include <cstdint>

#define MAXN 50000
#define MAXE 1600000

// ---- scratch (static device globals: allocation-free) ----
// INVARIANT: g_deg is zero at every kernel_launch entry (statically zero;
// the FINAL mlp2 epilogue re-zeros it each call).
// g_se is padded by 32 entries (always zero => src 0 / edge 0: valid reads)
// so gather lookahead loads need no clamping.
__device__ float g_h [MAXN * 128];
__device__ float g_t [MAXN * 128];   // MLP hidden scratch (L2-resident)
__device__ float g_hA[MAXN * 128];
__device__ float g_hB[MAXN * 128];
__device__ int   g_deg[MAXN];
__device__ int   g_rowptr[MAXN + 1];
__device__ int   g_src[MAXE];
__device__ int   g_dst[MAXE];
__device__ int2  g_se[MAXE + 32];   // (src, edge_id) sorted by dst, padded

// ---- packed f32x2 helpers ----
typedef unsigned long long u64;

__device__ __forceinline__ u64 pack2(float lo, float hi) {
    u64 r;
    asm("mov.b64 %0, {%1, %2};" : "=l"(r) : "f"(lo), "f"(hi));
    return r;
}
__device__ __forceinline__ void unpack2(u64 v, float& lo, float& hi) {
    asm("mov.b64 {%0, %1}, %2;" : "=f"(lo), "=f"(hi) : "l"(v));
}
__device__ __forceinline__ u64 ffma2(u64 a, u64 b, u64 c) {
    u64 d;
    asm("fma.rn.f32x2 %0, %1, %2, %3;" : "=l"(d) : "l"(a), "l"(b), "l"(c));
    return d;
}

// ---- cp.async helpers (smem address precomputed as u32) ----
__device__ __forceinline__ void cp_async16s(unsigned sdst, const void* src) {
    asm volatile("cp.async.cg.shared.global [%0], [%1], 16;" :: "r"(sdst), "l"(src));
}
__device__ __forceinline__ void cp_commit() {
    asm volatile("cp.async.commit_group;");
}
template <int N> __device__ __forceinline__ void cp_wait() {
    asm volatile("cp.async.wait_group %0;" :: "n"(N));
}

// ---------------------------------------------------------------------------
// Launch 1: int32 convert (+dtype sniff per block) + dst histogram
// ---------------------------------------------------------------------------
__global__ void convert_hist_kernel(const void* __restrict__ ei, int E_, int N_) {
    __shared__ int bad;
    if (threadIdx.x == 0) bad = 0;
    __syncthreads();
    const long long* p64 = (const long long*)ei;
    int cnt = 0;
    for (int i = threadIdx.x; i < 512; i += blockDim.x) {
        long long v = p64[i];
        if (v < 0 || v >= (long long)N_) cnt++;
    }
    if (cnt) atomicAdd(&bad, cnt);
    __syncthreads();
    bool is64 = (bad < 256);

    int e = blockIdx.x * blockDim.x + threadIdx.x;
    if (e >= E_) return;
    int s, d;
    if (is64) {
        s = (int)p64[e]; d = (int)p64[E_ + e];
    } else {
        const int* p = (const int*)ei;
        s = p[e]; d = p[E_ + e];
    }
    g_src[e] = s;
    g_dst[e] = d;
    atomicAdd(&g_deg[d], 1);
}

// ---------------------------------------------------------------------------
// Launch 2: single-block exclusive scan of g_deg -> g_rowptr
// ---------------------------------------------------------------------------
__global__ void __launch_bounds__(1024) scan_kernel(int N_) {
    __shared__ int sh[1024];
    int tid = threadIdx.x;
    int chunk = (N_ + 1023) / 1024;
    int lo = tid * chunk;
    int hi = min(lo + chunk, N_);

    int sum = 0;
    for (int i = lo; i < hi; i++) sum += g_deg[i];
    sh[tid] = sum;
    __syncthreads();
    #pragma unroll
    for (int off = 1; off < 1024; off <<= 1) {
        int t = (tid >= off) ? sh[tid - off] : 0;
        __syncthreads();
        sh[tid] += t;
        __syncthreads();
    }
    int run = (tid > 0) ? sh[tid - 1] : 0;
    for (int i = lo; i < hi; i++) {
        run += g_deg[i];
        g_rowptr[i + 1] = run;
    }
    if (tid == 0) g_rowptr[0] = 0;
}

// ---------------------------------------------------------------------------
// Launch 3: scatter (src, edge_id) — DESTRUCTIVE rowptr cursor:
// pos = atomicAdd(&rowptr[d], 1). Afterwards rowptr[d] == old rowptr[d+1],
// so consumers read beg = (n ? rowptr[n-1] : 0), end = rowptr[n].
// ---------------------------------------------------------------------------
__global__ void scatter_kernel(int E_) {
    int e = blockIdx.x * blockDim.x + threadIdx.x;
    if (e >= E_) return;
    int d = g_dst[e];
    int pos = atomicAdd(&g_rowptr[d], 1);
    g_se[pos] = make_int2(g_src[e], e);
}

// ---------------------------------------------------------------------------
// Gather: one warp per 64 channels of a node (R10 pipeline — best measured).
//   D=64 : 1 warp/node.  D=128 : 2 warps/node (disjoint channel halves).
// Row bounds from the post-scatter (shifted) rowptr.
//   h[n] = x[n] + sum_e relu( x[src_e] + ea_e @ We + be )
// ---------------------------------------------------------------------------
template <int D>
__global__ void __launch_bounds__(256, 4) gather_kernel(
    const float* __restrict__ xp, int xs, const float* __restrict__ ea,
    const float* __restrict__ We, const float* __restrict__ be, int N_)
{
    constexpr int WPN = D / 64;
    __shared__ __align__(16) float s_ea[8][2][8][16];   // [warp][stage][edge][k]
    __shared__ __align__(16) float s_x [8][2][8][64];   // [warp][stage][edge][ch]

    const float* __restrict__ x = xp ? xp : (xs == 0 ? g_hA : g_hB);
    int w = threadIdx.x >> 5;
    int lane = threadIdx.x & 31;
    int gw = blockIdx.x * 8 + w;
    int n = gw / WPN;
    if (n >= N_) return;
    int half = gw - n * WPN;
    int chbase = half * 64;
    int ch0 = chbase + lane * 2;

    // K-pair-packed weights for this lane's 2 channels (32 regs)
    u64 wp0[8], wp1[8];
    #pragma unroll
    for (int k2 = 0; k2 < 8; k2++) {
        wp0[k2] = pack2(We[(2 * k2) * D + ch0],     We[(2 * k2 + 1) * D + ch0]);
        wp1[k2] = pack2(We[(2 * k2) * D + ch0 + 1], We[(2 * k2 + 1) * D + ch0 + 1]);
    }
    float b0 = be[ch0], b1 = be[ch0 + 1];

    int beg = (n > 0) ? g_rowptr[n - 1] : 0;   // shifted rowptr (post-scatter)
    int end = g_rowptr[n];
    float a0 = 0.f, a1 = 0.f;
    int nch = (end - beg + 7) >> 3;

    unsigned sea_b = (unsigned)__cvta_generic_to_shared(&s_ea[w][0][0][0]);
    unsigned sx_b  = (unsigned)__cvta_generic_to_shared(&s_x [w][0][0][0]);
    int jr = lane >> 2, q4 = lane & 3;       // ea: 1 float4 per lane
    int jx = lane >> 4, qx = lane & 15;      // x : 4 float4 per lane
    int j8 = lane & 7;

    auto issue_chunk = [&](int st, int2 pr) {
        int eid = __shfl_sync(0xFFFFFFFFu, pr.y, jr);
        cp_async16s(sea_b + st * 512 + jr * 64 + q4 * 16,
                    ea + (size_t)eid * 16 + q4 * 4);
        #pragma unroll
        for (int t = 0; t < 4; t++) {
            int j = jx + t * 2;
            int src = __shfl_sync(0xFFFFFFFFu, pr.x, j);
            cp_async16s(sx_b + st * 2048 + j * 256 + qx * 16,
                        x + (size_t)src * D + chbase + qx * 4);
        }
        cp_commit();
    };

    if (nch > 0) {
        int2 p_cur = g_se[beg + j8];                 // unclamped (padded array)
        issue_chunk(0, p_cur);
        int2 p_nxt = make_int2(0, 0);
        if (nch > 1) p_nxt = g_se[beg + 8 + j8];

        for (int c = 0; c < nch; c++) {
            if (c + 1 < nch) issue_chunk((c + 1) & 1, p_nxt);
            int2 p_fut = make_int2(0, 0);
            if (c + 2 < nch) p_fut = g_se[beg + (c + 2) * 8 + j8];
            if (c + 1 < nch) cp_wait<1>(); else cp_wait<0>();
            __syncwarp();

            int cnt = min(8, end - (beg + c * 8));
            int st = c & 1;
            for (int j = 0; j < cnt; j++) {
                float2 xv = *(const float2*)&s_x[w][st][j][lane * 2];
                const ulonglong2* er2 = (const ulonglong2*)s_ea[w][st][j];
                ulonglong2 u0 = er2[0], u1 = er2[1], u2 = er2[2], u3 = er2[3];
                u64 s0 = pack2(b0, xv.x);   // bias/x folded into accumulator
                u64 s1 = pack2(b1, xv.y);
                s0 = ffma2(u0.x, wp0[0], s0); s1 = ffma2(u0.x, wp1[0], s1);
                s0 = ffma2(u0.y, wp0[1], s0); s1 = ffma2(u0.y, wp1[1], s1);
                s0 = ffma2(u1.x, wp0[2], s0); s1 = ffma2(u1.x, wp1[2], s1);
                s0 = ffma2(u1.y, wp0[3], s0); s1 = ffma2(u1.y, wp1[3], s1);
                s0 = ffma2(u2.x, wp0[4], s0); s1 = ffma2(u2.x, wp1[4], s1);
                s0 = ffma2(u2.y, wp0[5], s0); s1 = ffma2(u2.y, wp1[5], s1);
                s0 = ffma2(u3.x, wp0[6], s0); s1 = ffma2(u3.x, wp1[6], s1);
                s0 = ffma2(u3.y, wp0[7], s0); s1 = ffma2(u3.y, wp1[7], s1);
                float l0, h0, l1, h1;
                unpack2(s0, l0, h0);
                unpack2(s1, l1, h1);
                a0 += fmaxf(l0 + h0, 0.f);
                a1 += fmaxf(l1 + h1, 0.f);
            }
            p_cur = p_nxt;
            p_nxt = p_fut;
            __syncwarp();   // all lanes done with stage st before it is reissued
        }
    }

    float2 xn = *(const float2*)(x + (size_t)n * D + ch0);
    *(float2*)(g_h + (size_t)n * D + ch0) = make_float2(a0 + xn.x, a1 + xn.y);
}

// ---------------------------------------------------------------------------
// MLP phase 1: t = relu(h @ W1 + b1)   (g_h -> g_t); 2 blocks/SM.
// ---------------------------------------------------------------------------
template <int DIN>
__global__ void __launch_bounds__(256, 2) mlp1_kernel(
    const float* __restrict__ W1, const float* __restrict__ b1, int N_)
{
    extern __shared__ u64 smu[];
    u64* sWp = smu;                             // (DIN/2)*128 u64
    float* sb = (float*)(sWp + (DIN / 2) * 128);// 128
    float* sH = sb + 128;                       // 64*DIN

    int tid = threadIdx.x;
    for (int i = tid; i < (DIN / 2) * 128; i += 256) {
        int k2 = i >> 7, c = i & 127;
        sWp[i] = pack2(W1[(2 * k2) * 128 + c], W1[(2 * k2 + 1) * 128 + c]);
    }
    if (tid < 128) sb[tid] = b1[tid];
    __syncthreads();

    int tx = tid & 31;
    int ty = tid >> 5;

    const int ntiles = (N_ + 63) / 64;
    for (int tile = blockIdx.x; tile < ntiles; tile += gridDim.x) {
        int base = tile * 64;

        constexpr int C4 = DIN / 4;
        for (int i4 = tid; i4 < 64 * C4; i4 += 256) {
            int r = i4 / C4;
            int c4 = i4 - r * C4;
            int gr = base + r;
            float4 v = make_float4(0.f, 0.f, 0.f, 0.f);
            if (gr < N_) v = ((const float4*)g_h)[(size_t)gr * C4 + c4];
            ((float4*)sH)[i4] = v;
        }
        __syncthreads();

        u64 acc[8][4];
        #pragma unroll
        for (int r = 0; r < 8; r++)
            #pragma unroll
            for (int j = 0; j < 4; j++) acc[r][j] = 0ULL;
        #pragma unroll 2
        for (int k4 = 0; k4 < DIN / 4; k4++) {
            int k2a = 2 * k4;
            const ulonglong2* wra = (const ulonglong2*)(sWp + k2a * 128);
            const ulonglong2* wrb = (const ulonglong2*)(sWp + (k2a + 1) * 128);
            ulonglong2 wa01 = wra[tx * 2], wa23 = wra[tx * 2 + 1];
            ulonglong2 wb01 = wrb[tx * 2], wb23 = wrb[tx * 2 + 1];
            u64 wA[4] = {wa01.x, wa01.y, wa23.x, wa23.y};
            u64 wB[4] = {wb01.x, wb01.y, wb23.x, wb23.y};
            ulonglong2 a2[8];
            #pragma unroll
            for (int r = 0; r < 8; r++)
                a2[r] = *(const ulonglong2*)(sH + (ty * 8 + r) * DIN + 4 * k4);
            #pragma unroll
            for (int r = 0; r < 8; r++)
                #pragma unroll
                for (int j = 0; j < 4; j++) {
                    acc[r][j] = ffma2(a2[r].x, wA[j], acc[r][j]);
                    acc[r][j] = ffma2(a2[r].y, wB[j], acc[r][j]);
                }
        }
        float bb[4];
        #pragma unroll
        for (int j = 0; j < 4; j++) bb[j] = sb[tx * 4 + j];
        #pragma unroll
        for (int r = 0; r < 8; r++) {
            int gr = base + ty * 8 + r;
            if (gr < N_) {
                float v[4];
                #pragma unroll
                for (int j = 0; j < 4; j++) {
                    float lo, hi;
                    unpack2(acc[r][j], lo, hi);
                    v[j] = fmaxf(lo + hi + bb[j], 0.f);
                }
                ((float4*)(g_t + (size_t)gr * 128))[tx] =
                    make_float4(v[0], v[1], v[2], v[3]);
            }
        }
        __syncthreads();
    }
}

// ---------------------------------------------------------------------------
// MLP phase 2: h = relu(t @ W2 + b2).
//   FINAL=false: store h to g_hA/g_hB.
//   FINAL=true : fused tail — out[n] = sigmoid(h[n].Wlin + blin) via in-warp
//                shfl reduction (h never stored), then re-zero g_deg.
// ---------------------------------------------------------------------------
template <bool FINAL>
__global__ void __launch_bounds__(256, 2) mlp2_kernel(
    int os, const float* __restrict__ W2, const float* __restrict__ b2,
    const float* __restrict__ Wlin, const float* __restrict__ blin,
    float* __restrict__ outp_final, int N_)
{
    extern __shared__ u64 smu[];
    u64* sWp = smu;                             // 64*128 u64
    float* sb = (float*)(sWp + 64 * 128);       // 128
    float* sWl = sb + 128;                      // 128 (Wlin, FINAL only)
    float* sT = sWl + 128;                      // 64*128

    int tid = threadIdx.x;
    for (int i = tid; i < 64 * 128; i += 256) {
        int k2 = i >> 7, c = i & 127;
        sWp[i] = pack2(W2[(2 * k2) * 128 + c], W2[(2 * k2 + 1) * 128 + c]);
    }
    if (tid < 128) {
        sb[tid] = b2[tid];
        if (FINAL) sWl[tid] = Wlin[tid];
    }
    __syncthreads();

    float* outp = (os == 0) ? g_hA : g_hB;
    float bl = FINAL ? blin[0] : 0.f;
    int tx = tid & 31;
    int ty = tid >> 5;

    const int ntiles = (N_ + 63) / 64;
    for (int tile = blockIdx.x; tile < ntiles; tile += gridDim.x) {
        int base = tile * 64;

        for (int i4 = tid; i4 < 64 * 32; i4 += 256) {
            int r = i4 >> 5;
            int c4 = i4 & 31;
            int gr = base + r;
            float4 v = make_float4(0.f, 0.f, 0.f, 0.f);
            if (gr < N_) v = ((const float4*)g_t)[(size_t)gr * 32 + c4];
            ((float4*)sT)[i4] = v;
        }
        __syncthreads();

        u64 acc[8][4];
        #pragma unroll
        for (int r = 0; r < 8; r++)
            #pragma unroll
            for (int j = 0; j < 4; j++) acc[r][j] = 0ULL;
        #pragma unroll 2
        for (int k4 = 0; k4 < 32; k4++) {
            int k2a = 2 * k4;
            const ulonglong2* wra = (const ulonglong2*)(sWp + k2a * 128);
            const ulonglong2* wrb = (const ulonglong2*)(sWp + (k2a + 1) * 128);
            ulonglong2 wa01 = wra[tx * 2], wa23 = wra[tx * 2 + 1];
            ulonglong2 wb01 = wrb[tx * 2], wb23 = wrb[tx * 2 + 1];
            u64 wA[4] = {wa01.x, wa01.y, wa23.x, wa23.y};
            u64 wB[4] = {wb01.x, wb01.y, wb23.x, wb23.y};
            ulonglong2 a2[8];
            #pragma unroll
            for (int r = 0; r < 8; r++)
                a2[r] = *(const ulonglong2*)(sT + (ty * 8 + r) * 128 + 4 * k4);
            #pragma unroll
            for (int r = 0; r < 8; r++)
                #pragma unroll
                for (int j = 0; j < 4; j++) {
                    acc[r][j] = ffma2(a2[r].x, wA[j], acc[r][j]);
                    acc[r][j] = ffma2(a2[r].y, wB[j], acc[r][j]);
                }
        }
        float bb[4];
        #pragma unroll
        for (int j = 0; j < 4; j++) bb[j] = sb[tx * 4 + j];

        if (!FINAL) {
            #pragma unroll
            for (int r = 0; r < 8; r++) {
                int gr = base + ty * 8 + r;
                if (gr < N_) {
                    float v[4];
                    #pragma unroll
                    for (int j = 0; j < 4; j++) {
                        float lo, hi;
                        unpack2(acc[r][j], lo, hi);
                        v[j] = fmaxf(lo + hi + bb[j], 0.f);
                    }
                    ((float4*)(outp + (size_t)gr * 128))[tx] =
                        make_float4(v[0], v[1], v[2], v[3]);
                }
            }
        } else {
            float wl[4];
            #pragma unroll
            for (int j = 0; j < 4; j++) wl[j] = sWl[tx * 4 + j];
            #pragma unroll
            for (int r = 0; r < 8; r++) {
                float part = 0.f;
                #pragma unroll
                for (int j = 0; j < 4; j++) {
                    float lo, hi;
                    unpack2(acc[r][j], lo, hi);
                    part = fmaf(fmaxf(lo + hi + bb[j], 0.f), wl[j], part);
                }
                #pragma unroll
                for (int o = 16; o; o >>= 1)
                    part += __shfl_xor_sync(0xFFFFFFFFu, part, o);
                int gr = base + ty * 8 + r;
                if (tx == 0 && gr < N_)
                    outp_final[gr] = 1.f / (1.f + expf(-(part + bl)));
            }
        }
        __syncthreads();
    }

    // restore zero-invariant for next call (grid*256 >= N_)
    if (FINAL) {
        int gtid = blockIdx.x * 256 + tid;
        if (gtid < N_) g_deg[gtid] = 0;
    }
}

// ---------------------------------------------------------------------------
extern "C" void kernel_launch(void* const* d_in, const int* in_sizes, int n_in,
                              void* d_out, int out_size)
{
    const float* x   = (const float*)d_in[0];
    const void*  ei  = d_in[1];
    const float* ea  = (const float*)d_in[2];
    const float* We0 = (const float*)d_in[3];
    const float* be0 = (const float*)d_in[4];
    const float* W10 = (const float*)d_in[5];
    const float* b10 = (const float*)d_in[6];
    const float* W20 = (const float*)d_in[7];
    const float* b20 = (const float*)d_in[8];
    const float* We1 = (const float*)d_in[9];
    const float* be1 = (const float*)d_in[10];
    const float* W11 = (const float*)d_in[11];
    const float* b11 = (const float*)d_in[12];
    const float* W21 = (const float*)d_in[13];
    const float* b21 = (const float*)d_in[14];
    const float* We2 = (const float*)d_in[15];
    const float* be2 = (const float*)d_in[16];
    const float* W12 = (const float*)d_in[17];
    const float* b12 = (const float*)d_in[18];
    const float* W22 = (const float*)d_in[19];
    const float* b22 = (const float*)d_in[20];
    const float* Wln = (const float*)d_in[21];
    const float* bln = (const float*)d_in[22];

    int N_ = in_sizes[0] / 64;
    int E_ = in_sizes[2] / 16;

    constexpr int SM1_64  = (32 * 128) * 8 + 512 + (64 * 64) * 4;
    constexpr int SM1_128 = (64 * 128) * 8 + 512 + (64 * 128) * 4;
    constexpr int SM2     = (64 * 128) * 8 + 1024 + (64 * 128) * 4;
    cudaFuncSetAttribute(mlp1_kernel<64>,  cudaFuncAttributeMaxDynamicSharedMemorySize, SM1_64);
    cudaFuncSetAttribute(mlp1_kernel<128>, cudaFuncAttributeMaxDynamicSharedMemorySize, SM1_128);
    cudaFuncSetAttribute(mlp2_kernel<false>, cudaFuncAttributeMaxDynamicSharedMemorySize, SM2);
    cudaFuncSetAttribute(mlp2_kernel<true>,  cudaFuncAttributeMaxDynamicSharedMemorySize, SM2);

    int ebc = (E_ + 255) / 256;
    int gb64  = (N_ * 1 + 7) / 8;     // 1 warp/node, 8 warps/block
    int gb128 = (N_ * 2 + 7) / 8;     // 2 warps/node
    const int MGRID = 296;            // 148 SMs x 2 blocks (>= N_/256 threads)

    // ---- CSR build (g_deg zero by invariant) ----
    convert_hist_kernel<<<ebc, 256>>>(ei, E_, N_);      // launch 1
    scan_kernel<<<1, 1024>>>(N_);                       // launch 2
    scatter_kernel<<<ebc, 256>>>(E_);                   // launch 3 (shifts rowptr)

    // ---- layer 0 (d = 64) ----
    gather_kernel<64><<<gb64, 256>>>(x, 0, ea, We0, be0, N_);       // launch 4
    mlp1_kernel<64><<<MGRID, 256, SM1_64>>>(W10, b10, N_);
    mlp2_kernel<false><<<MGRID, 256, SM2>>>(0, W20, b20, nullptr, nullptr, nullptr, N_);

    // ---- layer 1 (d = 128) ----
    gather_kernel<128><<<gb128, 256>>>(nullptr, 0, ea, We1, be1, N_);
    mlp1_kernel<128><<<MGRID, 256, SM1_128>>>(W11, b11, N_);
    mlp2_kernel<false><<<MGRID, 256, SM2>>>(1, W21, b21, nullptr, nullptr, nullptr, N_);

    // ---- layer 2 (d = 128) + fused final linear/sigmoid + g_deg re-zero ----
    gather_kernel<128><<<gb128, 256>>>(nullptr, 1, ea, We2, be2, N_);
    mlp1_kernel<128><<<MGRID, 256, SM1_128>>>(W12, b12, N_);
    mlp2_kernel<true><<<MGRID, 256, SM2>>>(0, W22, b22, Wln, bln, (float*)d_out, N_);
}